// round 1
// baseline (speedup 1.0000x reference)
#include <cuda_runtime.h>

#define B_   2
#define S_   256
#define K_   2
#define IN_  512
#define OUT_ 512
#define NB_  16
#define M_TOTAL (B_ * S_ * K_)   // 1024 rows total

#define TM 64   // rows per m-tile
#define TN 64   // output cols per CTA
#define KC 64   // k-chunk

// Scratch for binning (device globals: no allocation allowed in kernel_launch)
__device__ int g_cnt[NB_];
__device__ int g_rows[NB_][M_TOTAL];

// ---------------------------------------------------------------------------
// Kernel 1: bucket the 1024 (b,s,k) rows by selected bank.
// Re-zeroes counts every launch so graph replays are deterministic.
// ---------------------------------------------------------------------------
__global__ void bin_kernel(const int* __restrict__ sel) {
    int tid = threadIdx.x;
    if (tid < NB_) g_cnt[tid] = 0;
    __syncthreads();
    if (tid < M_TOTAL) {
        int g = sel[tid];
        int pos = atomicAdd(&g_cnt[g], 1);
        g_rows[g][pos] = tid;
    }
}

// ---------------------------------------------------------------------------
// Kernel 2: grouped GEMM. CTA = (n_tile, bank). Loops over that bank's rows
// in m-tiles of 64. SMEM tiles 64x64, 4x4 register micro-tile per thread.
// ---------------------------------------------------------------------------
__global__ __launch_bounds__(256) void gemm_kernel(
    const float* __restrict__ x,      // (1024, IN)
    const float* __restrict__ w,      // (NB, OUT, IN)
    const float* __restrict__ bias,   // (NB, OUT)
    float* __restrict__ out)          // (1024, OUT)
{
    const int g  = blockIdx.y;
    const int n0 = blockIdx.x * TN;
    const int cnt = g_cnt[g];
    if (cnt == 0) return;

    __shared__ float xs[TM][KC + 1];
    __shared__ float ws[TN][KC + 1];
    __shared__ int   rows_s[TM];

    const int tid = threadIdx.x;
    const int tx  = tid & 15;   // 0..15 -> col group
    const int ty  = tid >> 4;   // 0..15 -> row group

    const float* __restrict__ wg = w + (size_t)g * OUT_ * IN_;

    for (int m0 = 0; m0 < cnt; m0 += TM) {
        __syncthreads();  // prior epilogue / compute done before rows_s rewrite
        const int mlen = min(TM, cnt - m0);
        if (tid < TM) rows_s[tid] = (tid < mlen) ? g_rows[g][m0 + tid] : -1;

        float acc[4][4] = {};

        for (int k0 = 0; k0 < IN_; k0 += KC) {
            __syncthreads();  // rows_s ready; previous tile fully consumed

            // Load W tile: TN x KC (4096 elems, 16 per thread), coalesced over kk
            #pragma unroll
            for (int i = 0; i < (TN * KC) / 256; i++) {
                int idx = tid + i * 256;
                int o  = idx / KC;
                int kk = idx % KC;
                ws[o][kk] = wg[(size_t)(n0 + o) * IN_ + k0 + kk];
            }
            // Load X tile: TM x KC (gather rows via rows_s), coalesced over kk
            #pragma unroll
            for (int i = 0; i < (TM * KC) / 256; i++) {
                int idx = tid + i * 256;
                int m  = idx / KC;
                int kk = idx % KC;
                int r  = rows_s[m];
                xs[m][kk] = (r >= 0) ? x[(size_t)r * IN_ + k0 + kk] : 0.0f;
            }
            __syncthreads();

            #pragma unroll
            for (int kk = 0; kk < KC; kk++) {
                float a[4], bb[4];
                #pragma unroll
                for (int i = 0; i < 4; i++) a[i]  = xs[ty * 4 + i][kk];
                #pragma unroll
                for (int j = 0; j < 4; j++) bb[j] = ws[tx * 4 + j][kk];
                #pragma unroll
                for (int i = 0; i < 4; i++)
                    #pragma unroll
                    for (int j = 0; j < 4; j++)
                        acc[i][j] += a[i] * bb[j];
            }
        }

        // Epilogue: add bias, scatter to the row's output slot
        #pragma unroll
        for (int i = 0; i < 4; i++) {
            int r = rows_s[ty * 4 + i];
            if (r < 0) continue;
            #pragma unroll
            for (int j = 0; j < 4; j++) {
                int col = n0 + tx * 4 + j;
                out[(size_t)r * OUT_ + col] = acc[i][j] + bias[g * OUT_ + col];
            }
        }
    }
}

// ---------------------------------------------------------------------------
extern "C" void kernel_launch(void* const* d_in, const int* in_sizes, int n_in,
                              void* d_out, int out_size) {
    const float* tensor = (const float*)d_in[0];   // (B,S,K,IN) fp32
    const int*   sel    = (const int*)  d_in[1];   // (B,S,K) int32
    const float* weight = (const float*)d_in[2];   // (NB,OUT,IN) fp32
    const float* bias   = (const float*)d_in[3];   // (NB,OUT) fp32
    float*       out    = (float*)d_out;           // (B,S,K,OUT) fp32

    bin_kernel<<<1, 1024>>>(sel);
    dim3 grid(OUT_ / TN, NB_);   // (8, 16) = 128 CTAs
    gemm_kernel<<<grid, 256>>>(tensor, weight, bias, out);
}

// round 3
// speedup vs baseline: 2.9570x; 2.9570x over previous
#include <cuda_runtime.h>
#include <cuda_bf16.h>
#include <cstdint>

#define IN_      512
#define OUT_     512
#define NB_      16
#define M_TOTAL  1024
#define TM       64
#define TN       64
#define KC       64
#define NTHREADS 256

// ---------------- binning scratch ----------------
__device__ int g_cnt[NB_];
__device__ int g_rows[NB_][M_TOTAL];

__global__ void bin_kernel(const int* __restrict__ sel) {
    __shared__ int c[NB_];
    int tid = threadIdx.x;
    if (tid < NB_) c[tid] = 0;
    __syncthreads();
    int g = sel[tid];
    int pos = atomicAdd(&c[g], 1);
    g_rows[g][pos] = tid;
    __syncthreads();
    if (tid < NB_) g_cnt[tid] = c[tid];
}

// ---------------- PTX helpers ----------------
__device__ __forceinline__ uint32_t smem_u32(const void* p) {
    uint32_t a;
    asm("{ .reg .u64 t; cvta.to.shared.u64 t, %1; cvt.u32.u64 %0, t; }" : "=r"(a) : "l"(p));
    return a;
}
__device__ __forceinline__ void ldsm4(uint32_t* r, uint32_t addr) {
    asm volatile("ldmatrix.sync.aligned.m8n8.x4.shared.b16 {%0,%1,%2,%3}, [%4];"
        : "=r"(r[0]), "=r"(r[1]), "=r"(r[2]), "=r"(r[3]) : "r"(addr));
}
__device__ __forceinline__ void mma_bf16(float* c, const uint32_t* a, uint32_t b0, uint32_t b1) {
    asm volatile("mma.sync.aligned.m16n8k16.row.col.f32.bf16.bf16.f32 "
        "{%0,%1,%2,%3}, {%4,%5,%6,%7}, {%8,%9}, {%0,%1,%2,%3};"
        : "+f"(c[0]), "+f"(c[1]), "+f"(c[2]), "+f"(c[3])
        : "r"(a[0]), "r"(a[1]), "r"(a[2]), "r"(a[3]), "r"(b0), "r"(b1));
}

// split float4 into bf16-hi (rounded) and bf16-lo (residual) packed pairs
__device__ __forceinline__ void split4(float4 v, uint2& hi, uint2& lo) {
    __nv_bfloat16 hx = __float2bfloat16_rn(v.x);
    __nv_bfloat16 hy = __float2bfloat16_rn(v.y);
    __nv_bfloat16 hz = __float2bfloat16_rn(v.z);
    __nv_bfloat16 hw = __float2bfloat16_rn(v.w);
    float rx = v.x - __bfloat162float(hx);
    float ry = v.y - __bfloat162float(hy);
    float rz = v.z - __bfloat162float(hz);
    float rw = v.w - __bfloat162float(hw);
    __nv_bfloat162 h01 = __halves2bfloat162(hx, hy);
    __nv_bfloat162 h23 = __halves2bfloat162(hz, hw);
    __nv_bfloat162 l01 = __halves2bfloat162(__float2bfloat16_rn(rx), __float2bfloat16_rn(ry));
    __nv_bfloat162 l23 = __halves2bfloat162(__float2bfloat16_rn(rz), __float2bfloat16_rn(rw));
    hi.x = *reinterpret_cast<uint32_t*>(&h01);
    hi.y = *reinterpret_cast<uint32_t*>(&h23);
    lo.x = *reinterpret_cast<uint32_t*>(&l01);
    lo.y = *reinterpret_cast<uint32_t*>(&l23);
}

// ---------------- grouped GEMM (bf16-split HMMA) ----------------
__global__ __launch_bounds__(NTHREADS) void gemm_kernel(
    const float* __restrict__ x,      // (1024, IN)
    const float* __restrict__ w,      // (NB, OUT, IN)
    const float* __restrict__ bias,   // (NB, OUT)
    float* __restrict__ out)          // (1024, OUT)
{
    // bf16 planes: 128 bytes (64 bf16) per row, SW128-style swizzled
    __shared__ __align__(128) uint8_t sAh[TM * 128], sAl[TM * 128];
    __shared__ __align__(128) uint8_t sBh[TN * 128], sBl[TN * 128];
    __shared__ int   rows_s[TM];
    __shared__ float bias_s[TN];

    const int tid = threadIdx.x;
    const int lid = tid & 31, wid = tid >> 5;
    const int warp_m = wid & 3;        // 4 m-warps x 16 rows
    const int warp_n = wid >> 2;       // 2 n-warps x 32 cols
    const int g  = blockIdx.y;
    const int n0 = blockIdx.x * TN;
    const int cnt = g_cnt[g];
    if (cnt == 0) return;

    if (tid < TN) bias_s[tid] = bias[g * OUT_ + n0 + tid];
    const float* __restrict__ wg = w + (size_t)g * OUT_ * IN_;

    const uint32_t sAh_b = smem_u32(sAh), sAl_b = smem_u32(sAl);
    const uint32_t sBh_b = smem_u32(sBh), sBl_b = smem_u32(sBl);

    // per-thread gmem/smem staging geometry (4 rows per thread, stride 16)
    const int rbase = tid >> 4;                    // 0..15
    const int c4    = (tid & 15) * 4;              // k offset (floats)
    const uint32_t st_sw = (uint32_t)((tid & 15) * 8) ^ (uint32_t)((rbase & 7) * 16);

    // ldmatrix addresses (constant parts)
    const uint32_t swx   = (uint32_t)(lid & 7) * 16;
    const uint32_t khalf = (uint32_t)(lid >> 4) * 16;
    const uint32_t a_off  = (uint32_t)(warp_m * 16 + (lid & 15)) * 128;
    const uint32_t b0_off = (uint32_t)(warp_n * 32 + (lid & 15)) * 128;
    const uint32_t b1_off = b0_off + 16 * 128;

    const float4 f4z = make_float4(0.f, 0.f, 0.f, 0.f);

    for (int m0 = 0; m0 < cnt; m0 += TM) {
        __syncthreads();   // previous epilogue done; smem/rows_s free
        if (tid < TM) rows_s[tid] = (m0 + tid < cnt) ? g_rows[g][m0 + tid] : -1;
        __syncthreads();

        float4 av[4], bv[4];
        // prefetch chunk 0
        #pragma unroll
        for (int j = 0; j < 4; j++) {
            int rowA = rbase + j * 16;
            int r = rows_s[rowA];
            av[j] = (r >= 0) ? *(const float4*)&x[(size_t)r * IN_ + c4] : f4z;
            bv[j] = *(const float4*)&wg[(size_t)(n0 + rowA) * IN_ + c4];
        }

        float acc[4][4] = {};

        #pragma unroll 1
        for (int t = 0; t < IN_ / KC; t++) {
            // ---- store staged chunk into bf16 hi/lo planes ----
            #pragma unroll
            for (int j = 0; j < 4; j++) {
                int rowA = rbase + j * 16;
                uint32_t soff = (uint32_t)rowA * 128 + st_sw;
                uint2 hi, lo;
                split4(av[j], hi, lo);
                *(uint2*)(sAh + soff) = hi;
                *(uint2*)(sAl + soff) = lo;
                split4(bv[j], hi, lo);
                *(uint2*)(sBh + soff) = hi;
                *(uint2*)(sBl + soff) = lo;
            }
            __syncthreads();

            // ---- prefetch next chunk (overlaps with MMA below) ----
            if (t < IN_ / KC - 1) {
                int k0 = (t + 1) * KC + c4;
                #pragma unroll
                for (int j = 0; j < 4; j++) {
                    int rowA = rbase + j * 16;
                    int r = rows_s[rowA];
                    av[j] = (r >= 0) ? *(const float4*)&x[(size_t)r * IN_ + k0] : f4z;
                    bv[j] = *(const float4*)&wg[(size_t)(n0 + rowA) * IN_ + k0];
                }
            }

            // ---- compute: 4 k16 steps ----
            #pragma unroll
            for (int s = 0; s < 4; s++) {
                uint32_t koff = ((uint32_t)(khalf + s * 32)) ^ swx;
                uint32_t ah[4], al[4], bh0[4], bh1[4], bl0[4], bl1[4];
                ldsm4(ah,  sAh_b + a_off  + koff);
                ldsm4(al,  sAl_b + a_off  + koff);
                ldsm4(bh0, sBh_b + b0_off + koff);
                ldsm4(bh1, sBh_b + b1_off + koff);
                ldsm4(bl0, sBl_b + b0_off + koff);
                ldsm4(bl1, sBl_b + b1_off + koff);

                uint32_t bhx[4][2] = {{bh0[0], bh0[2]}, {bh0[1], bh0[3]},
                                      {bh1[0], bh1[2]}, {bh1[1], bh1[3]}};
                uint32_t blx[4][2] = {{bl0[0], bl0[2]}, {bl0[1], bl0[3]},
                                      {bl1[0], bl1[2]}, {bl1[1], bl1[3]}};
                #pragma unroll
                for (int nf = 0; nf < 4; nf++) {
                    mma_bf16(acc[nf], ah, bhx[nf][0], bhx[nf][1]);  // hi*hi
                    mma_bf16(acc[nf], ah, blx[nf][0], blx[nf][1]);  // hi*lo
                    mma_bf16(acc[nf], al, bhx[nf][0], bhx[nf][1]);  // lo*hi
                }
            }
            __syncthreads();   // planes fully consumed before next overwrite
        }

        // ---- epilogue: scatter rows with bias ----
        {
            int gq = lid >> 2, tq = lid & 3;
            int r0 = rows_s[warp_m * 16 + gq];
            int r1 = rows_s[warp_m * 16 + gq + 8];
            #pragma unroll
            for (int nf = 0; nf < 4; nf++) {
                int col = warp_n * 32 + nf * 8 + tq * 2;
                float bb0 = bias_s[col], bb1 = bias_s[col + 1];
                if (r0 >= 0) {
                    float2 v = make_float2(acc[nf][0] + bb0, acc[nf][1] + bb1);
                    *(float2*)&out[(size_t)r0 * OUT_ + n0 + col] = v;
                }
                if (r1 >= 0) {
                    float2 v = make_float2(acc[nf][2] + bb0, acc[nf][3] + bb1);
                    *(float2*)&out[(size_t)r1 * OUT_ + n0 + col] = v;
                }
            }
        }
    }
}

// ---------------------------------------------------------------------------
extern "C" void kernel_launch(void* const* d_in, const int* in_sizes, int n_in,
                              void* d_out, int out_size) {
    const float* tensor = (const float*)d_in[0];   // (B,S,K,IN) fp32
    const int*   sel    = (const int*)  d_in[1];   // (B,S,K) int32
    const float* weight = (const float*)d_in[2];   // (NB,OUT,IN) fp32
    const float* bias   = (const float*)d_in[3];   // (NB,OUT) fp32
    float*       out    = (float*)d_out;           // (B,S,K,OUT) fp32

    bin_kernel<<<1, M_TOTAL>>>(sel);
    dim3 grid(OUT_ / TN, NB_);   // (8, 16) = 128 CTAs
    gemm_kernel<<<grid, NTHREADS>>>(tensor, weight, bias, out);
}

// round 5
// speedup vs baseline: 3.8854x; 1.3140x over previous
#include <cuda_runtime.h>
#include <cuda_bf16.h>
#include <cstdint>

#define IN_      512
#define OUT_     512
#define NB_      16
#define M_TOTAL  1024
#define TM       64
#define TN       64
#define NTHREADS 256

// dynamic smem layout (bytes)
#define PLANE     8192                    // 64 rows * 128 B (64 bf16/row)
#define BUF_BYTES (4 * PLANE)             // Ah, Al, Bh, Bl planes
#define OFF_ROWS  (2 * BUF_BYTES)         // 65536: int rows_bank[1024]
#define OFF_BIAS  (OFF_ROWS + M_TOTAL * 4)// 69632: float bias_s[64]
#define SMEM_TOTAL (OFF_BIAS + TN * 4)    // 69888

// ---------------- PTX helpers ----------------
__device__ __forceinline__ uint32_t smem_u32(const void* p) {
    uint32_t a;
    asm("{ .reg .u64 t; cvta.to.shared.u64 t, %1; cvt.u32.u64 %0, t; }" : "=r"(a) : "l"(p));
    return a;
}
__device__ __forceinline__ void ldsm4(uint32_t* r, uint32_t addr) {
    asm volatile("ldmatrix.sync.aligned.m8n8.x4.shared.b16 {%0,%1,%2,%3}, [%4];"
        : "=r"(r[0]), "=r"(r[1]), "=r"(r[2]), "=r"(r[3]) : "r"(addr));
}
__device__ __forceinline__ void mma_bf16(float* c, const uint32_t* a, uint32_t b0, uint32_t b1) {
    asm volatile("mma.sync.aligned.m16n8k16.row.col.f32.bf16.bf16.f32 "
        "{%0,%1,%2,%3}, {%4,%5,%6,%7}, {%8,%9}, {%0,%1,%2,%3};"
        : "+f"(c[0]), "+f"(c[1]), "+f"(c[2]), "+f"(c[3])
        : "r"(a[0]), "r"(a[1]), "r"(a[2]), "r"(a[3]), "r"(b0), "r"(b1));
}

// split float4 into bf16-hi (rounded) and bf16-lo (residual) packed pairs
__device__ __forceinline__ void split4(float4 v, uint2& hi, uint2& lo) {
    __nv_bfloat16 hx = __float2bfloat16_rn(v.x);
    __nv_bfloat16 hy = __float2bfloat16_rn(v.y);
    __nv_bfloat16 hz = __float2bfloat16_rn(v.z);
    __nv_bfloat16 hw = __float2bfloat16_rn(v.w);
    float rx = v.x - __bfloat162float(hx);
    float ry = v.y - __bfloat162float(hy);
    float rz = v.z - __bfloat162float(hz);
    float rw = v.w - __bfloat162float(hw);
    __nv_bfloat162 h01 = __halves2bfloat162(hx, hy);
    __nv_bfloat162 h23 = __halves2bfloat162(hz, hw);
    __nv_bfloat162 l01 = __halves2bfloat162(__float2bfloat16_rn(rx), __float2bfloat16_rn(ry));
    __nv_bfloat162 l23 = __halves2bfloat162(__float2bfloat16_rn(rz), __float2bfloat16_rn(rw));
    hi.x = *reinterpret_cast<uint32_t*>(&h01);
    hi.y = *reinterpret_cast<uint32_t*>(&h23);
    lo.x = *reinterpret_cast<uint32_t*>(&l01);
    lo.y = *reinterpret_cast<uint32_t*>(&l23);
}

// ---------------- fused binning + grouped GEMM (bf16-split HMMA) -------------
__global__ __launch_bounds__(NTHREADS, 2) void gemm_kernel(
    const float* __restrict__ x,      // (1024, IN)
    const int*   __restrict__ sel,    // (1024,)
    const float* __restrict__ w,      // (NB, OUT, IN)
    const float* __restrict__ bias,   // (NB, OUT)
    float* __restrict__ out)          // (1024, OUT)
{
    extern __shared__ __align__(128) uint8_t smem[];
    int*   rows_bank = (int*)(smem + OFF_ROWS);
    float* bias_s    = (float*)(smem + OFF_BIAS);
    __shared__ int warp_base[8];
    __shared__ int cnt_s;

    const int tid = threadIdx.x;
    const int lid = tid & 31, wid = tid >> 5;
    const int warp_m = wid & 3;        // 4 m-warps x 16 rows
    const int warp_n = wid >> 2;       // 2 n-warps x 32 cols
    const int g  = blockIdx.y;
    const int n0 = blockIdx.x * TN;
    const int mz = blockIdx.z;         // m-slice within bank

    // ---- DETERMINISTIC binning: stable compaction of rows with sel==g ----
    // Thread tid owns sel indices [tid*4, tid*4+4) in order. Identical
    // ordering in every CTA -> the mz split is consistent across CTAs.
    {
        int4 sv = *(const int4*)&sel[tid * 4];
        int m0f = (sv.x == g), m1f = (sv.y == g), m2f = (sv.z == g), m3f = (sv.w == g);
        int lc = m0f + m1f + m2f + m3f;
        // warp inclusive scan
        int inc = lc;
        #pragma unroll
        for (int d = 1; d < 32; d <<= 1) {
            int nv = __shfl_up_sync(0xffffffffu, inc, d);
            if (lid >= d) inc += nv;
        }
        if (lid == 31) warp_base[wid] = inc;
        __syncthreads();
        if (tid == 0) {
            int acc = 0;
            #pragma unroll
            for (int i = 0; i < 8; i++) { int v = warp_base[i]; warp_base[i] = acc; acc += v; }
            cnt_s = acc;
        }
        __syncthreads();
        int p = warp_base[wid] + inc - lc;   // exclusive rank
        if (m0f) rows_bank[p++] = tid * 4 + 0;
        if (m1f) rows_bank[p++] = tid * 4 + 1;
        if (m2f) rows_bank[p++] = tid * 4 + 2;
        if (m3f) rows_bank[p++] = tid * 4 + 3;
    }
    if (tid < TN) bias_s[tid] = bias[g * OUT_ + n0 + tid];
    __syncthreads();
    const int cnt = cnt_s;
    if (mz * TM >= cnt) return;

    const float* __restrict__ wg = w + (size_t)g * OUT_ * IN_;
    const uint32_t sm_b = smem_u32(smem);

    // staging geometry: 4 rows per thread (stride 16), 4 floats each
    const int rbase = tid >> 4;                       // 0..15
    const int c4    = (tid & 15) * 4;                 // k offset (floats)
    const uint32_t st_sw = (uint32_t)((tid & 15) * 8) ^ (uint32_t)((rbase & 7) * 16);

    // ldmatrix constant address parts
    const uint32_t swx   = (uint32_t)(lid & 7) * 16;
    const uint32_t khalf = (uint32_t)(lid >> 4) * 16;
    const uint32_t a_off  = (uint32_t)(warp_m * 16 + (lid & 15)) * 128;
    const uint32_t b0_off = (uint32_t)(warp_n * 32 + (lid & 15)) * 128;
    const uint32_t b1_off = b0_off + 16 * 128;

    const float4 f4z = make_float4(0.f, 0.f, 0.f, 0.f);

    for (int m0 = mz * TM; m0 < cnt; m0 += 2 * TM) {
        int rA[4];
        #pragma unroll
        for (int j = 0; j < 4; j++) {
            int m = m0 + rbase + j * 16;
            rA[j] = (m < cnt) ? rows_bank[m] : -1;
        }

        float4 av[4], bv[4];
        #pragma unroll
        for (int j = 0; j < 4; j++) {   // prefetch chunk 0
            int rowA = rbase + j * 16;
            av[j] = (rA[j] >= 0) ? *(const float4*)&x[(size_t)rA[j] * IN_ + c4] : f4z;
            bv[j] = *(const float4*)&wg[(size_t)(n0 + rowA) * IN_ + c4];
        }

        float acc[4][4] = {};

        #pragma unroll 1
        for (int t = 0; t < IN_ / 64; t++) {          // 8 k-chunks of 64
            const uint32_t bufB = (uint32_t)(t & 1) * BUF_BYTES;
            uint8_t* bb = smem + bufB;

            // ---- stage chunk t into bf16 hi/lo planes of buf[t&1] ----
            #pragma unroll
            for (int j = 0; j < 4; j++) {
                uint32_t soff = (uint32_t)(rbase + j * 16) * 128 + st_sw;
                uint2 hi, lo;
                split4(av[j], hi, lo);
                *(uint2*)(bb + soff)          = hi;   // Ah
                *(uint2*)(bb + PLANE + soff)  = lo;   // Al
                split4(bv[j], hi, lo);
                *(uint2*)(bb + 2 * PLANE + soff) = hi; // Bh
                *(uint2*)(bb + 3 * PLANE + soff) = lo; // Bl
            }
            __syncthreads();   // one barrier per chunk (double-buffered)

            // ---- prefetch chunk t+1 (overlaps compute below) ----
            if (t < IN_ / 64 - 1) {
                int k0 = (t + 1) * 64 + c4;
                #pragma unroll
                for (int j = 0; j < 4; j++) {
                    int rowA = rbase + j * 16;
                    av[j] = (rA[j] >= 0) ? *(const float4*)&x[(size_t)rA[j] * IN_ + k0] : f4z;
                    bv[j] = *(const float4*)&wg[(size_t)(n0 + rowA) * IN_ + k0];
                }
            }

            // ---- compute chunk t: 4 k16 steps, 3-product bf16 split ----
            const uint32_t ah_b = sm_b + bufB + a_off;
            const uint32_t al_b = ah_b + PLANE;
            const uint32_t bh_b = sm_b + bufB + 2 * PLANE;
            const uint32_t bl_b = bh_b + PLANE;
            #pragma unroll
            for (int s = 0; s < 4; s++) {
                uint32_t koff = ((uint32_t)(khalf + s * 32)) ^ swx;
                uint32_t ah[4], al[4], bh0[4], bh1[4], bl0[4], bl1[4];
                ldsm4(ah,  ah_b + koff);
                ldsm4(al,  al_b + koff);
                ldsm4(bh0, bh_b + b0_off + koff);
                ldsm4(bh1, bh_b + b1_off + koff);
                ldsm4(bl0, bl_b + b0_off + koff);
                ldsm4(bl1, bl_b + b1_off + koff);

                uint32_t bhx[4][2] = {{bh0[0], bh0[2]}, {bh0[1], bh0[3]},
                                      {bh1[0], bh1[2]}, {bh1[1], bh1[3]}};
                uint32_t blx[4][2] = {{bl0[0], bl0[2]}, {bl0[1], bl0[3]},
                                      {bl1[0], bl1[2]}, {bl1[1], bl1[3]}};
                #pragma unroll
                for (int nf = 0; nf < 4; nf++) {
                    mma_bf16(acc[nf], ah, bhx[nf][0], bhx[nf][1]);  // hi*hi
                    mma_bf16(acc[nf], ah, blx[nf][0], blx[nf][1]);  // hi*lo
                    mma_bf16(acc[nf], al, bhx[nf][0], bhx[nf][1]);  // lo*hi
                }
            }
            // next stage writes the other buffer; the per-chunk barrier
            // guarantees all warps left compute(t-1) on that buffer.
        }

        // ---- epilogue: scatter rows with bias ----
        {
            int gq = lid >> 2, tq = lid & 3;
            int m_lo = m0 + warp_m * 16 + gq;
            int r0 = (m_lo     < cnt) ? rows_bank[m_lo]     : -1;
            int r1 = (m_lo + 8 < cnt) ? rows_bank[m_lo + 8] : -1;
            #pragma unroll
            for (int nf = 0; nf < 4; nf++) {
                int col = warp_n * 32 + nf * 8 + tq * 2;
                float bb0 = bias_s[col], bb1 = bias_s[col + 1];
                if (r0 >= 0) {
                    float2 v = make_float2(acc[nf][0] + bb0, acc[nf][1] + bb1);
                    *(float2*)&out[(size_t)r0 * OUT_ + n0 + col] = v;
                }
                if (r1 >= 0) {
                    float2 v = make_float2(acc[nf][2] + bb0, acc[nf][3] + bb1);
                    *(float2*)&out[(size_t)r1 * OUT_ + n0 + col] = v;
                }
            }
        }
    }
}

// ---------------------------------------------------------------------------
extern "C" void kernel_launch(void* const* d_in, const int* in_sizes, int n_in,
                              void* d_out, int out_size) {
    const float* tensor = (const float*)d_in[0];   // (B,S,K,IN) fp32
    const int*   sel    = (const int*)  d_in[1];   // (B,S,K) int32
    const float* weight = (const float*)d_in[2];   // (NB,OUT,IN) fp32
    const float* bias   = (const float*)d_in[3];   // (NB,OUT) fp32
    float*       out    = (float*)d_out;           // (B,S,K,OUT) fp32

    cudaFuncSetAttribute(gemm_kernel, cudaFuncAttributeMaxDynamicSharedMemorySize, SMEM_TOTAL);
    dim3 grid(OUT_ / TN, NB_, 2);   // (8, 16, 2) = 256 CTAs, one wave @ 2 CTA/SM
    gemm_kernel<<<grid, NTHREADS, SMEM_TOTAL>>>(tensor, sel, weight, bias, out);
}